// round 7
// baseline (speedup 1.0000x reference)
#include <cuda_runtime.h>
#include <math.h>

#define BB 8
#define NN 1000
#define CC 81
#define FG 80           // foreground classes
#define KK 100
#define MSZ 28
#define NPROB (BB*FG)   // 640
#define IMG_W 1216.0f
#define IMG_H 800.0f
#define SCORE_TH 0.05f
#define NMS_TH 0.5f
#define CLIPV 4.135166556742356f   // log(1000/16)
#define CAP 4096
#define NB 1024         // select histogram bins
#define CB 512          // collect buffer cap
#define BIN_BASE 0x3D4C // float bits top-16 of 0.05
#define GRID 640
#define THR 256

// ---- scratch (no allocations allowed) ----
__device__ int                g_cnt[NPROB];
__device__ int                g_kcnt[NPROB];
__device__ float              g_score[NPROB*NN];
__device__ float              g_box[NPROB*NN*4];
__device__ unsigned           g_nidx[NPROB*NN];
__device__ unsigned long long g_keys[NPROB*NN];
__device__ int                g_labels[BB*KK];
__device__ unsigned           g_arrive;   // barrier arrive counter (returns to 0)
__device__ unsigned           g_gen;      // barrier generation (monotonic)

// software grid barrier — requires all GRID blocks resident (proven by occupancy)
__device__ __forceinline__ void grid_sync() {
    __syncthreads();
    if (threadIdx.x == 0) {
        unsigned gen = *(volatile unsigned*)&g_gen;
        __threadfence();
        if (atomicAdd(&g_arrive, 1u) == GRID - 1u) {
            g_arrive = 0;
            __threadfence();
            *(volatile unsigned*)&g_gen = gen + 1u;
        } else {
            while (*(volatile unsigned*)&g_gen == gen) { __nanosleep(64); }
        }
        __threadfence();
    }
    __syncthreads();
}

struct NmsView {
    unsigned long long skey[1024];
    int   spay[1024];
    float sx0[NN], sy0[NN], sx1[NN], sy1[NN], ssc[NN];
    int   skept[NN];
};
struct TopkView {
    unsigned long long keys[CAP];
    unsigned long long cbuf[CB];
    int hist[NB];
    int scnt[FG];
    int soff[FG + 1];
    int sth, sccnt;
};
union SmemU { NmsView nms; TopkView tk; };

__device__ __forceinline__ void bitonic_desc(unsigned long long* a, int n2, int tid, int nthr) {
    for (int k = 2; k <= n2; k <<= 1) {
        for (int j = k >> 1; j > 0; j >>= 1) {
            for (int i = tid; i < n2; i += nthr) {
                int ix = i ^ j;
                if (ix > i) {
                    bool up = ((i & k) == 0);
                    unsigned long long x = a[i], y = a[ix];
                    bool sw = up ? (x < y) : (x > y);
                    if (sw) { a[i] = y; a[ix] = x; }
                }
            }
            __syncthreads();
        }
    }
}

__global__ void __launch_bounds__(THR, 5)
k_all(const float* __restrict__ logits, const float* __restrict__ reg,
      const float* __restrict__ props,  const float* __restrict__ ml,
      float* __restrict__ out) {
    __shared__ SmemU sm;
    int tid  = threadIdx.x;
    int lane = tid & 31;
    int wib  = tid >> 5;                       // warp in block (0..7)
    int gwarp = blockIdx.x * (THR/32) + wib;   // 0..5119

    // ================= Phase 1: softmax + decode + candidate append =========
    for (int row = gwarp; row < BB*NN; row += GRID*(THR/32)) {
        const float* lg = logits + (size_t)row * CC;
        float v0 = lg[lane];
        float v1 = lg[lane + 32];
        float v2 = (lane + 64 < CC) ? lg[lane + 64] : -3.402823466e38f;

        float mx = fmaxf(fmaxf(v0, v1), v2);
        #pragma unroll
        for (int o = 16; o; o >>= 1) mx = fmaxf(mx, __shfl_xor_sync(0xFFFFFFFFu, mx, o));
        float e0 = expf(v0 - mx), e1 = expf(v1 - mx);
        float e2 = (lane + 64 < CC) ? expf(v2 - mx) : 0.f;
        float sum = e0 + e1 + e2;
        #pragma unroll
        for (int o = 16; o; o >>= 1) sum += __shfl_xor_sync(0xFFFFFFFFu, sum, o);
        float inv = 1.0f / sum;

        float p0 = props[row*4+0], p1 = props[row*4+1];
        float p2 = props[row*4+2], p3 = props[row*4+3];
        float w = p2 - p0, h = p3 - p1;
        float cx = p0 + 0.5f * w, cy = p1 + 0.5f * h;
        int b = row / NN, n = row % NN;

        #pragma unroll
        for (int u = 0; u < 3; u++) {
            int c = lane + u * 32;
            if (c == 0 || c >= CC) continue;
            float sc = (u == 0 ? e0 : (u == 1 ? e1 : e2)) * inv;
            if (sc > SCORE_TH) {
                const float* r = reg + (size_t)row * (CC*4) + c*4;
                float dx = r[0] * 0.1f, dy = r[1] * 0.1f;
                float dw = fminf(r[2] * 0.2f, CLIPV);
                float dh = fminf(r[3] * 0.2f, CLIPV);
                float pcx = dx * w + cx, pcy = dy * h + cy;
                float pw = expf(dw) * w, ph = expf(dh) * h;
                float x0 = fminf(fmaxf(pcx - 0.5f * pw, 0.f), IMG_W);
                float y0 = fminf(fmaxf(pcy - 0.5f * ph, 0.f), IMG_H);
                float x1 = fminf(fmaxf(pcx + 0.5f * pw, 0.f), IMG_W);
                float y1 = fminf(fmaxf(pcy + 0.5f * ph, 0.f), IMG_H);
                int prob = b * FG + (c - 1);
                int slot = atomicAdd(&g_cnt[prob], 1);
                int base = prob * NN + slot;
                g_score[base] = sc;
                g_box[base*4+0] = x0; g_box[base*4+1] = y0;
                g_box[base*4+2] = x1; g_box[base*4+3] = y1;
                g_nidx[base] = (unsigned)n;
            }
        }
    }

    grid_sync();

    // ================= Phase 2: per-(image,class) sort + greedy NMS ==========
    {
        int prob = blockIdx.x;                  // exactly 640 problems
        int c = prob % FG;
        int m = g_cnt[prob];
        if (m > NN) m = NN;

        int n2 = 32; while (n2 < m) n2 <<= 1;

        for (int i = tid; i < n2; i += THR) {
            if (i < m) {
                float sc = g_score[prob*NN + i];
                unsigned nb = g_nidx[prob*NN + i];
                sm.nms.skey[i] = ((unsigned long long)__float_as_uint(sc) << 32)
                               | (unsigned long long)(0xFFFFFFFFu - nb);
                sm.nms.spay[i] = i;
            } else { sm.nms.skey[i] = 0ull; sm.nms.spay[i] = 0; }
        }
        __syncthreads();

        for (int k = 2; k <= n2; k <<= 1) {
            for (int j = k >> 1; j > 0; j >>= 1) {
                for (int i = tid; i < n2; i += THR) {
                    int ix = i ^ j;
                    if (ix > i) {
                        bool up = ((i & k) == 0);
                        unsigned long long a = sm.nms.skey[i], bk = sm.nms.skey[ix];
                        bool sw = up ? (a < bk) : (a > bk);
                        if (sw) {
                            sm.nms.skey[i] = bk; sm.nms.skey[ix] = a;
                            int t = sm.nms.spay[i]; sm.nms.spay[i] = sm.nms.spay[ix]; sm.nms.spay[ix] = t;
                        }
                    }
                }
                __syncthreads();
            }
        }

        for (int i = tid; i < m; i += THR) {
            int p = prob*NN + sm.nms.spay[i];
            sm.nms.ssc[i] = __uint_as_float((unsigned)(sm.nms.skey[i] >> 32));
            sm.nms.sx0[i] = g_box[p*4+0]; sm.nms.sy0[i] = g_box[p*4+1];
            sm.nms.sx1[i] = g_box[p*4+2]; sm.nms.sy1[i] = g_box[p*4+3];
            sm.nms.skept[i] = 1;
        }
        __syncthreads();

        for (int i = 0; i < m; i++) {
            if (sm.nms.skept[i]) {
                float bx0 = sm.nms.sx0[i], by0 = sm.nms.sy0[i];
                float bx1 = sm.nms.sx1[i], by1 = sm.nms.sy1[i];
                float a1 = (bx1 - bx0) * (by1 - by0);
                for (int j = i + 1 + tid; j < m; j += THR) {
                    if (!sm.nms.skept[j]) continue;
                    float lx = fmaxf(bx0, sm.nms.sx0[j]);
                    float ly = fmaxf(by0, sm.nms.sy0[j]);
                    float rx = fminf(bx1, sm.nms.sx1[j]);
                    float ry = fminf(by1, sm.nms.sy1[j]);
                    float iw = fmaxf(rx - lx, 0.f);
                    float ih = fmaxf(ry - ly, 0.f);
                    float inter = iw * ih;
                    float a2 = (sm.nms.sx1[j] - sm.nms.sx0[j]) * (sm.nms.sy1[j] - sm.nms.sy0[j]);
                    float iou = inter / (a1 + a2 - inter + 1e-9f);
                    if (iou > NMS_TH) sm.nms.skept[j] = 0;
                }
            }
            __syncthreads();
        }

        for (int i = tid; i < m; i += THR) {
            int base = prob*NN + i;
            g_box[base*4+0] = sm.nms.sx0[i]; g_box[base*4+1] = sm.nms.sy0[i];
            g_box[base*4+2] = sm.nms.sx1[i]; g_box[base*4+3] = sm.nms.sy1[i];
            if (sm.nms.skept[i]) {
                int pos = atomicAdd(&g_kcnt[prob], 1);
                unsigned fl = (unsigned)(c * NN + i);
                g_keys[prob*NN + pos] =
                    ((unsigned long long)__float_as_uint(sm.nms.ssc[i]) << 32)
                  | (unsigned long long)(0xFFFFFFFFu - fl);
            }
        }
        if (tid == 0) g_cnt[prob] = 0;          // reset for next replay
    }

    grid_sync();

    // ================= Phase 3: per-image radix-select top-100 ===============
    if (blockIdx.x < BB) {
        int b = blockIdx.x;

        if (tid < FG) {
            int p = b * FG + tid;
            sm.tk.scnt[tid] = min(g_kcnt[p], NN);
            g_kcnt[p] = 0;                      // reset for next replay
        }
        if (tid == 0) { sm.tk.sth = -1; sm.tk.sccnt = 0; }
        #pragma unroll
        for (int r = 0; r < NB/THR; r++) sm.tk.hist[tid + r*THR] = 0;
        __syncthreads();
        if (tid == 0) {
            int acc = 0;
            for (int c2 = 0; c2 < FG; c2++) { sm.tk.soff[c2] = acc; acc += sm.tk.scnt[c2]; }
            sm.tk.soff[FG] = acc;
        }
        __syncthreads();
        int L = sm.tk.soff[FG]; if (L > CAP) L = CAP;

        // 8 warps: warp w copies classes w, w+8, ...
        for (int c2 = wib; c2 < FG; c2 += 8) {
            int off = sm.tk.soff[c2], cnt = sm.tk.scnt[c2];
            const unsigned long long* src = g_keys + (size_t)(b * FG + c2) * NN;
            for (int i = lane; i < cnt; i += 32) {
                int d = off + i;
                if (d < CAP) sm.tk.keys[d] = src[i];
            }
        }
        __syncthreads();

        for (int i = tid; i < L; i += THR) {
            int bin = (int)(sm.tk.keys[i] >> 48) - BIN_BASE;
            bin = max(0, min(NB - 1, bin));
            atomicAdd(&sm.tk.hist[bin], 1);
        }
        __syncthreads();

        // suffix sums over 1024 bins with 256 threads (4 bins/thread)
        for (int d = 1; d < NB; d <<= 1) {
            int v[NB/THR];
            #pragma unroll
            for (int r = 0; r < NB/THR; r++) {
                int i = tid + r*THR;
                v[r] = (i + d < NB) ? sm.tk.hist[i + d] : 0;
            }
            __syncthreads();
            #pragma unroll
            for (int r = 0; r < NB/THR; r++) sm.tk.hist[tid + r*THR] += v[r];
            __syncthreads();
        }

        #pragma unroll
        for (int r = 0; r < NB/THR; r++) {
            int i = tid + r*THR;
            if (sm.tk.hist[i] >= KK && (i == NB - 1 || sm.tk.hist[i + 1] < KK)) sm.tk.sth = i;
        }
        __syncthreads();

        int t = sm.tk.sth;
        bool fast = (t >= 0) && (sm.tk.hist[t] <= CB);

        const unsigned long long* srt;
        if (fast) {
            for (int i = tid; i < L; i += THR) {
                int bin = (int)(sm.tk.keys[i] >> 48) - BIN_BASE;
                bin = max(0, min(NB - 1, bin));
                if (bin >= t) {
                    int pos = atomicAdd(&sm.tk.sccnt, 1);
                    sm.tk.cbuf[pos] = sm.tk.keys[i];
                }
            }
            __syncthreads();
            int cnum = sm.tk.sccnt;
            int n2 = 128; while (n2 < cnum) n2 <<= 1;
            for (int i = cnum + tid; i < n2; i += THR) sm.tk.cbuf[i] = 0ull;
            __syncthreads();
            bitonic_desc(sm.tk.cbuf, n2, tid, THR);
            srt = sm.tk.cbuf;
        } else {
            int n2 = 128; while (n2 < L) n2 <<= 1;
            for (int i = L + tid; i < n2; i += THR) sm.tk.keys[i] = 0ull;
            __syncthreads();
            bitonic_desc(sm.tk.keys, n2, tid, THR);
            srt = sm.tk.keys;
        }

        if (tid < KK) {
            unsigned long long key = srt[tid];
            float sc = __uint_as_float((unsigned)(key >> 32));
            float x0 = 0.f, y0 = 0.f, x1 = 0.f, y1 = 0.f, scw = 0.f;
            int label = 0;
            if (sc > 0.0f) {
                unsigned fl = 0xFFFFFFFFu - (unsigned)(key & 0xFFFFFFFFull);
                int c2 = (int)(fl / NN), i = (int)(fl % NN);
                int base = (b * FG + c2) * NN + i;
                x0 = g_box[base*4+0]; y0 = g_box[base*4+1];
                x1 = g_box[base*4+2]; y1 = g_box[base*4+3];
                scw = sc; label = c2 + 1;
            }
            int bk = b * KK + tid;
            out[bk*4+0] = x0; out[bk*4+1] = y0; out[bk*4+2] = x1; out[bk*4+3] = y1;
            out[BB*KK*4 + bk] = scw;                  // top_s
            out[BB*KK*4 + BB*KK + bk] = (float)label; // labels
            g_labels[bk] = label;
        }
    }

    grid_sync();

    // ================= Phase 4: mask gather + sigmoid (all blocks) ===========
    {
        const int TOT4 = BB*KK*(MSZ*MSZ/4);    // 156800 float4
        float* mout = out + (BB*KK*4 + 2*BB*KK);
        for (int idx = blockIdx.x * THR + tid; idx < TOT4; idx += GRID*THR) {
            int bk = idx / (MSZ*MSZ/4);
            int t4 = idx % (MSZ*MSZ/4);
            int label = g_labels[bk];
            const float4* src = (const float4*)(ml + ((size_t)bk * CC + (size_t)label) * (MSZ*MSZ));
            float4 v = src[t4];
            v.x = 1.0f / (1.0f + expf(-v.x));
            v.y = 1.0f / (1.0f + expf(-v.y));
            v.z = 1.0f / (1.0f + expf(-v.z));
            v.w = 1.0f / (1.0f + expf(-v.w));
            ((float4*)(mout + (size_t)bk * (MSZ*MSZ)))[t4] = v;
        }
    }
}

extern "C" void kernel_launch(void* const* d_in, const int* in_sizes, int n_in,
                              void* d_out, int out_size) {
    (void)in_sizes; (void)n_in; (void)out_size;
    const float* logits = (const float*)d_in[0];
    const float* reg    = (const float*)d_in[1];
    const float* props  = (const float*)d_in[2];
    const float* ml     = (const float*)d_in[3];
    float* out = (float*)d_out;

    k_all<<<GRID, THR>>>(logits, reg, props, ml, out);
}

// round 8
// speedup vs baseline: 1.1075x; 1.1075x over previous
#include <cuda_runtime.h>
#include <math.h>

#define BB 8
#define NN 1000
#define CC 81
#define FG 80           // foreground classes
#define KK 100
#define MSZ 28
#define NPROB (BB*FG)   // 640
#define IMG_W 1216.0f
#define IMG_H 800.0f
#define SCORE_TH 0.05f
#define NMS_TH 0.5f
#define CLIPV 4.135166556742356f   // log(1000/16)
#define CAP 4096
#define NB 1024         // select histogram bins
#define CB 512          // collect buffer cap
#define BIN_BASE 0x3D4C // float bits top-16 of 0.05

// ---- scratch (no allocations allowed) ----
__device__ int                g_cnt[NPROB];          // candidates per (b,c)
__device__ int                g_kcnt[NPROB];         // kept after NMS per (b,c)
__device__ float              g_score[NPROB*NN];
__device__ float              g_box[NPROB*NN*4];
__device__ unsigned           g_nidx[NPROB*NN];
__device__ unsigned long long g_keys[NPROB*NN];      // compacted kept keys
__device__ int                g_labels[BB*KK];

// One warp per proposal row: softmax over 81 classes (register-cached),
// threshold, decode box, append candidate.
__global__ void k_softmax_cand(const float* __restrict__ logits,
                               const float* __restrict__ reg,
                               const float* __restrict__ props) {
    int warp = (blockIdx.x * blockDim.x + threadIdx.x) >> 5;
    int lane = threadIdx.x & 31;
    if (warp >= BB * NN) return;
    int row = warp;
    const float* lg = logits + (size_t)row * CC;

    float v0 = lg[lane];
    float v1 = lg[lane + 32];
    float v2 = (lane + 64 < CC) ? lg[lane + 64] : -3.402823466e38f;

    float mx = fmaxf(fmaxf(v0, v1), v2);
    #pragma unroll
    for (int o = 16; o; o >>= 1) mx = fmaxf(mx, __shfl_xor_sync(0xFFFFFFFFu, mx, o));
    float e0 = __expf(v0 - mx), e1 = __expf(v1 - mx);
    float e2 = (lane + 64 < CC) ? __expf(v2 - mx) : 0.f;
    float sum = e0 + e1 + e2;
    #pragma unroll
    for (int o = 16; o; o >>= 1) sum += __shfl_xor_sync(0xFFFFFFFFu, sum, o);
    float inv = 1.0f / sum;

    float p0 = props[row*4+0], p1 = props[row*4+1];
    float p2 = props[row*4+2], p3 = props[row*4+3];
    float w = p2 - p0, h = p3 - p1;
    float cx = p0 + 0.5f * w, cy = p1 + 0.5f * h;
    int b = row / NN, n = row % NN;

    #pragma unroll
    for (int u = 0; u < 3; u++) {
        int c = lane + u * 32;
        if (c == 0 || c >= CC) continue;
        float sc = (u == 0 ? e0 : (u == 1 ? e1 : e2)) * inv;
        if (sc > SCORE_TH) {
            const float* r = reg + (size_t)row * (CC*4) + c*4;
            float dx = r[0] * 0.1f, dy = r[1] * 0.1f;
            float dw = fminf(r[2] * 0.2f, CLIPV);
            float dh = fminf(r[3] * 0.2f, CLIPV);
            float pcx = dx * w + cx, pcy = dy * h + cy;
            float pw = expf(dw) * w, ph = expf(dh) * h;
            float x0 = fminf(fmaxf(pcx - 0.5f * pw, 0.f), IMG_W);
            float y0 = fminf(fmaxf(pcy - 0.5f * ph, 0.f), IMG_H);
            float x1 = fminf(fmaxf(pcx + 0.5f * pw, 0.f), IMG_W);
            float y1 = fminf(fmaxf(pcy + 0.5f * ph, 0.f), IMG_H);
            int prob = b * FG + (c - 1);
            int slot = atomicAdd(&g_cnt[prob], 1);
            int base = prob * NN + slot;
            g_score[base] = sc;
            g_box[base*4+0] = x0; g_box[base*4+1] = y0;
            g_box[base*4+2] = x1; g_box[base*4+3] = y1;
            g_nidx[base] = (unsigned)n;
        }
    }
}

// Per (image,class): sort candidates by (score desc, proposal idx asc) over
// next_pow2(m) elements, greedy NMS, compact kept keys to g_keys.
// Re-zeroes g_cnt[prob] at the end so the next replay starts clean.
__global__ void k_nms() {
    int prob = blockIdx.x;
    int c = prob % FG;
    int m = g_cnt[prob];
    if (m > NN) m = NN;
    __shared__ unsigned long long skey[1024];
    __shared__ int spay[1024];
    __shared__ float sx0[NN], sy0[NN], sx1[NN], sy1[NN], ssc[NN];
    __shared__ int skept[NN];
    int tid = threadIdx.x;
    const int NT = 128;

    int n2 = 32; while (n2 < m) n2 <<= 1;   // m<=1000 -> n2<=1024

    for (int i = tid; i < n2; i += NT) {
        if (i < m) {
            float sc = g_score[prob*NN + i];
            unsigned nb = g_nidx[prob*NN + i];
            skey[i] = ((unsigned long long)__float_as_uint(sc) << 32)
                    | (unsigned long long)(0xFFFFFFFFu - nb);
            spay[i] = i;
        } else { skey[i] = 0ull; spay[i] = 0; }
    }
    __syncthreads();

    for (int k = 2; k <= n2; k <<= 1) {
        for (int j = k >> 1; j > 0; j >>= 1) {
            for (int i = tid; i < n2; i += NT) {
                int ix = i ^ j;
                if (ix > i) {
                    bool up = ((i & k) == 0);
                    unsigned long long a = skey[i], bk = skey[ix];
                    bool sw = up ? (a < bk) : (a > bk);
                    if (sw) {
                        skey[i] = bk; skey[ix] = a;
                        int t = spay[i]; spay[i] = spay[ix]; spay[ix] = t;
                    }
                }
            }
            __syncthreads();
        }
    }

    for (int i = tid; i < m; i += NT) {
        int p = prob*NN + spay[i];
        ssc[i] = __uint_as_float((unsigned)(skey[i] >> 32));
        sx0[i] = g_box[p*4+0]; sy0[i] = g_box[p*4+1];
        sx1[i] = g_box[p*4+2]; sy1[i] = g_box[p*4+3];
        skept[i] = 1;
    }
    __syncthreads();

    // greedy NMS: only surviving boxes suppress; forward only (matches reference)
    for (int i = 0; i < m; i++) {
        if (skept[i]) {
            float bx0 = sx0[i], by0 = sy0[i], bx1 = sx1[i], by1 = sy1[i];
            float a1 = (bx1 - bx0) * (by1 - by0);
            for (int j = i + 1 + tid; j < m; j += NT) {
                if (!skept[j]) continue;
                float lx = fmaxf(bx0, sx0[j]);
                float ly = fmaxf(by0, sy0[j]);
                float rx = fminf(bx1, sx1[j]);
                float ry = fminf(by1, sy1[j]);
                float iw = fmaxf(rx - lx, 0.f);
                float ih = fmaxf(ry - ly, 0.f);
                float inter = iw * ih;
                float a2 = (sx1[j] - sx0[j]) * (sy1[j] - sy0[j]);
                float iou = inter / (a1 + a2 - inter + 1e-9f);
                if (iou > NMS_TH) skept[j] = 0;
            }
        }
        __syncthreads();
    }

    for (int i = tid; i < m; i += NT) {
        int base = prob*NN + i;
        g_box[base*4+0] = sx0[i]; g_box[base*4+1] = sy0[i];
        g_box[base*4+2] = sx1[i]; g_box[base*4+3] = sy1[i];
        if (skept[i]) {
            int pos = atomicAdd(&g_kcnt[prob], 1);
            unsigned fl = (unsigned)(c * NN + i);
            g_keys[prob*NN + pos] =
                ((unsigned long long)__float_as_uint(ssc[i]) << 32)
              | (unsigned long long)(0xFFFFFFFFu - fl);
        }
    }
    if (tid == 0) g_cnt[prob] = 0;   // reset for next replay
}

__device__ __forceinline__ void bitonic_desc(unsigned long long* a, int n2, int tid, int nthr) {
    for (int k = 2; k <= n2; k <<= 1) {
        for (int j = k >> 1; j > 0; j >>= 1) {
            for (int i = tid; i < n2; i += nthr) {
                int ix = i ^ j;
                if (ix > i) {
                    bool up = ((i & k) == 0);
                    unsigned long long x = a[i], y = a[ix];
                    bool sw = up ? (x < y) : (x > y);
                    if (sw) { a[i] = y; a[ix] = x; }
                }
            }
            __syncthreads();
        }
    }
}

// Per image: gather per-class kept keys, radix-select the top ~K by score
// high-bits, sort only the selected set, emit top-100. Fallback: full sort.
__global__ void k_topk(float* __restrict__ out) {
    int b = blockIdx.x;
    __shared__ unsigned long long keys[CAP];
    __shared__ unsigned long long cbuf[CB];
    __shared__ int hist[NB];
    __shared__ int scnt[FG];
    __shared__ int soff[FG + 1];
    __shared__ int sth, sccnt;
    int tid = threadIdx.x;
    int lane = tid & 31;
    int wid = tid >> 5;           // 32 warps @ 1024 threads

    if (tid < FG) {
        int p = b * FG + tid;
        scnt[tid] = min(g_kcnt[p], NN);
        g_kcnt[p] = 0;            // reset for next replay
    }
    if (tid == 0) { sth = -1; sccnt = 0; }
    hist[tid] = 0;
    __syncthreads();
    if (tid == 0) {
        int acc = 0;
        for (int c2 = 0; c2 < FG; c2++) { soff[c2] = acc; acc += scnt[c2]; }
        soff[FG] = acc;
    }
    __syncthreads();
    int L = soff[FG]; if (L > CAP) L = CAP;

    // warp w copies classes w, w+32, w+64
    for (int c2 = wid; c2 < FG; c2 += 32) {
        int off = soff[c2], cnt = scnt[c2];
        const unsigned long long* src = g_keys + (size_t)(b * FG + c2) * NN;
        for (int i = lane; i < cnt; i += 32) {
            int d = off + i;
            if (d < CAP) keys[d] = src[i];
        }
    }
    __syncthreads();

    // histogram on score top-16 bits (scores in (0.05,1) -> ~564 live bins)
    for (int i = tid; i < L; i += blockDim.x) {
        int bin = (int)(keys[i] >> 48) - BIN_BASE;
        bin = max(0, min(NB - 1, bin));
        atomicAdd(&hist[bin], 1);
    }
    __syncthreads();

    // suffix sum: hist[i] = #elements in bins >= i  (Hillis-Steele, 10 steps)
    #pragma unroll
    for (int d = 1; d < NB; d <<= 1) {
        int v = (tid + d < NB) ? hist[tid + d] : 0;
        __syncthreads();
        hist[tid] += v;
        __syncthreads();
    }

    // threshold bin: largest t with suffix(t) >= K
    if (hist[tid] >= KK && (tid == NB - 1 || hist[tid + 1] < KK)) sth = tid;
    __syncthreads();

    int t = sth;
    bool fast = (t >= 0) && (hist[t] <= CB);   // uniform across block

    const unsigned long long* srt;
    if (fast) {
        for (int i = tid; i < L; i += blockDim.x) {
            int bin = (int)(keys[i] >> 48) - BIN_BASE;
            bin = max(0, min(NB - 1, bin));
            if (bin >= t) {
                int pos = atomicAdd(&sccnt, 1);
                cbuf[pos] = keys[i];
            }
        }
        __syncthreads();
        int cnum = sccnt;
        int n2 = 128; while (n2 < cnum) n2 <<= 1;   // <= CB
        for (int i = cnum + tid; i < n2; i += blockDim.x) cbuf[i] = 0ull;
        __syncthreads();
        bitonic_desc(cbuf, n2, tid, blockDim.x);
        srt = cbuf;
    } else {
        int n2 = 128; while (n2 < L) n2 <<= 1;
        for (int i = L + tid; i < n2; i += blockDim.x) keys[i] = 0ull;
        __syncthreads();
        bitonic_desc(keys, n2, tid, blockDim.x);
        srt = keys;
    }

    if (tid < KK) {
        int k = tid;
        unsigned long long key = srt[k];
        float sc = __uint_as_float((unsigned)(key >> 32));
        float x0 = 0.f, y0 = 0.f, x1 = 0.f, y1 = 0.f, scw = 0.f;
        int label = 0;
        if (sc > 0.0f) {
            unsigned fl = 0xFFFFFFFFu - (unsigned)(key & 0xFFFFFFFFull);
            int c2 = (int)(fl / NN), i = (int)(fl % NN);
            int base = (b * FG + c2) * NN + i;
            x0 = g_box[base*4+0]; y0 = g_box[base*4+1];
            x1 = g_box[base*4+2]; y1 = g_box[base*4+3];
            scw = sc; label = c2 + 1;
        }
        int bk = b * KK + k;
        out[bk*4+0] = x0; out[bk*4+1] = y0; out[bk*4+2] = x1; out[bk*4+3] = y1;
        out[BB*KK*4 + bk] = scw;                  // top_s at 3200
        out[BB*KK*4 + BB*KK + bk] = (float)label; // labels at 4000
        g_labels[bk] = label;
    }
}

// sigmoid via HW tanh: 1 MUFU op instead of EX2+RCP (2 MUFU) — k_mask is MUFU-bound.
__device__ __forceinline__ float fast_sigmoid(float x) {
    float t;
    asm("tanh.approx.f32 %0, %1;" : "=f"(t) : "f"(x * 0.5f));
    return fmaf(t, 0.5f, 0.5f);
}

// Per detection: gather class channel of mask logits, sigmoid.
// 2 float4 per thread for ILP; 256-thread blocks; grid-stride over 156800 float4.
__global__ void k_mask(const float* __restrict__ ml, float* __restrict__ out) {
    const int TOT4 = BB*KK*(MSZ*MSZ/4);       // 156800
    float* mout = out + (BB*KK*4 + 2*BB*KK);
    int idx0 = (blockIdx.x * blockDim.x + threadIdx.x) * 2;

    #pragma unroll
    for (int u = 0; u < 2; u++) {
        int idx = idx0 + u;
        if (idx >= TOT4) break;
        int bk = idx / (MSZ*MSZ/4);
        int t4 = idx % (MSZ*MSZ/4);
        int label = g_labels[bk];
        const float4* src = (const float4*)(ml + ((size_t)bk * CC + (size_t)label) * (MSZ*MSZ));
        float4 v = src[t4];
        v.x = fast_sigmoid(v.x);
        v.y = fast_sigmoid(v.y);
        v.z = fast_sigmoid(v.z);
        v.w = fast_sigmoid(v.w);
        ((float4*)(mout + (size_t)bk * (MSZ*MSZ)))[t4] = v;
    }
}

extern "C" void kernel_launch(void* const* d_in, const int* in_sizes, int n_in,
                              void* d_out, int out_size) {
    (void)in_sizes; (void)n_in; (void)out_size;
    const float* logits = (const float*)d_in[0];
    const float* reg    = (const float*)d_in[1];
    const float* props  = (const float*)d_in[2];
    const float* ml     = (const float*)d_in[3];
    float* out = (float*)d_out;

    k_softmax_cand<<<(BB*NN + 7) / 8, 256>>>(logits, reg, props);
    k_nms<<<NPROB, 128>>>();
    k_topk<<<BB, 1024>>>(out);
    const int TOT4 = BB*KK*(MSZ*MSZ/4);
    k_mask<<<(TOT4/2 + 255) / 256, 256>>>(ml, out);
}